// round 2
// baseline (speedup 1.0000x reference)
#include <cuda_runtime.h>

// Deep-TEN encoding, fused FP32 kernel.
// B=64, N=4096, D=256, K=32. out = E [B,K,D] fp32.

#define Bb 64
#define Nn 4096
#define Dd 256
#define Kk 32
#define SPLIT 16
#define CHUNK (Nn / SPLIT)   // 256 points per block
#define TP 64                // points per smem tile
#define NTILES (CHUNK / TP)  // 4
#define CP 260               // C row pitch in floats (pitch % 32 == 4 -> conflict-free)
#define CP4 (CP / 4)         // 65
#define XP 260
#define XP4 (XP / 4)
#define WP 36                // w row pitch in floats
#define NTHR 256

struct SmemLayout {
    float Cs[Kk * CP];    // 33280 B
    float xs[TP * XP];    // 66560 B
    float ws[TP * WP];    //  9216 B
    float part[NTHR];     //  1024 B
    float x2s[TP];
    float c2s[Kk];
    float Ss[Kk];
};

__global__ __launch_bounds__(NTHR, 2)
void deepten_kernel(const float* __restrict__ x,
                    const float* __restrict__ Cg,
                    const float* __restrict__ Sg,
                    float* __restrict__ out)
{
    extern __shared__ unsigned char smem_raw[];
    SmemLayout* sm = reinterpret_cast<SmemLayout*>(smem_raw);

    const int tid  = threadIdx.x;
    const int warp = tid >> 5;
    const int lane = tid & 31;
    const int b     = blockIdx.y;
    const int slice = blockIdx.x;

    // ---- stage C (pitched float4) + S ----
    {
        const float4* C4 = reinterpret_cast<const float4*>(Cg);
        #pragma unroll
        for (int j = 0; j < (Kk * Dd / 4) / NTHR; ++j) {   // 8
            int idx = tid + j * NTHR;
            int k = idx >> 6, dc = idx & 63;
            *reinterpret_cast<float4*>(&sm->Cs[k * CP + dc * 4]) = C4[idx];
        }
        if (tid < Kk) sm->Ss[tid] = Sg[tid];
    }
    __syncthreads();
    // ---- c2[k] = sum_d C[k][d]^2 : lane-k mapping keeps LDS.128 conflict-free
    {
        int k = tid & 31, seg = tid >> 5;  // 8 segments of 8 float4
        const float4* row = reinterpret_cast<const float4*>(&sm->Cs[k * CP]);
        float s = 0.f;
        #pragma unroll
        for (int j = 0; j < 8; ++j) {
            float4 v = row[seg * 8 + j];
            s += v.x * v.x + v.y * v.y + v.z * v.z + v.w * v.w;
        }
        sm->part[tid] = s;
    }
    __syncthreads();
    if (tid < Kk) {
        float s = 0.f;
        #pragma unroll
        for (int q = 0; q < 8; ++q) s += sm->part[q * 32 + tid];
        sm->c2s[tid] = s;
    }
    // (covered by sync at top of tile loop)

    // phase-B ownership: warp kq owns k = 4*kq..4*kq+3; lane dq owns d = 4*dq..4*dq+3 and 128+4*dq..
    const int kq = warp;
    const int dq = lane;
    float4 acc[4][2];
    #pragma unroll
    for (int k = 0; k < 4; ++k) {
        acc[k][0] = make_float4(0.f, 0.f, 0.f, 0.f);
        acc[k][1] = make_float4(0.f, 0.f, 0.f, 0.f);
    }
    float4 wsum = make_float4(0.f, 0.f, 0.f, 0.f);

    for (int tile = 0; tile < NTILES; ++tile) {
        const int n0 = slice * CHUNK + tile * TP;
        __syncthreads();  // protect xs/ws reuse (and c2s on first tile)

        // ---- stage x tile: fully coalesced float4 ----
        {
            const float4* xg = reinterpret_cast<const float4*>(
                x + ((size_t)b * Nn + n0) * Dd);
            #pragma unroll
            for (int j = 0; j < (TP * Dd / 4) / NTHR; ++j) {  // 16
                int idx = tid + j * NTHR;
                int i = idx >> 6, dc = idx & 63;
                *reinterpret_cast<float4*>(&sm->xs[i * XP + dc * 4]) = xg[idx];
            }
        }
        __syncthreads();

        // ---- x2[i] = ||x_i||^2 : p = tid&63 keeps warp lanes on distinct rows
        {
            int p = tid & 63, q = tid >> 6;  // 4 segments of 16 float4
            const float4* row = reinterpret_cast<const float4*>(&sm->xs[p * XP]);
            float s = 0.f;
            #pragma unroll
            for (int j = 0; j < 16; ++j) {
                float4 v = row[q * 16 + j];
                s += v.x * v.x + v.y * v.y + v.z * v.z + v.w * v.w;
            }
            sm->part[tid] = s;
        }
        __syncthreads();
        if (tid < TP) {
            sm->x2s[tid] = sm->part[tid] + sm->part[tid + 64] +
                           sm->part[tid + 128] + sm->part[tid + 192];
        }
        __syncthreads();

        // ---- phase A: warp handles 8 points, lane = k ----
        {
            float xc[8];
            #pragma unroll
            for (int p = 0; p < 8; ++p) xc[p] = 0.f;
            const float4* crow = reinterpret_cast<const float4*>(&sm->Cs[lane * CP]);
            const float4* xrow = reinterpret_cast<const float4*>(&sm->xs[(warp * 8) * XP]);
            #pragma unroll 2
            for (int dc = 0; dc < 64; ++dc) {
                float4 c = crow[dc];
                #pragma unroll
                for (int p = 0; p < 8; ++p) {
                    float4 v = xrow[p * XP4 + dc];   // broadcast
                    xc[p] = fmaf(v.x, c.x, xc[p]);
                    xc[p] = fmaf(v.y, c.y, xc[p]);
                    xc[p] = fmaf(v.z, c.z, xc[p]);
                    xc[p] = fmaf(v.w, c.w, xc[p]);
                }
            }
            const float Sl  = sm->Ss[lane];
            const float c2l = sm->c2s[lane];
            #pragma unroll
            for (int p = 0; p < 8; ++p) {
                int pg = warp * 8 + p;
                float v = -Sl * (sm->x2s[pg] + c2l - 2.f * xc[p]);
                float m = v;
                #pragma unroll
                for (int off = 16; off; off >>= 1)
                    m = fmaxf(m, __shfl_xor_sync(0xffffffffu, m, off));
                float e = __expf(v - m);
                float s = e;
                #pragma unroll
                for (int off = 16; off; off >>= 1)
                    s += __shfl_xor_sync(0xffffffffu, s, off);
                sm->ws[pg * WP + lane] = e / s;
            }
        }
        __syncthreads();

        // ---- phase B: rank-64 update of the [32][256] register-tiled accumulator
        {
            #pragma unroll 2
            for (int i = 0; i < TP; ++i) {
                float4 wv = *reinterpret_cast<const float4*>(&sm->ws[i * WP + kq * 4]); // broadcast
                const float4* xr = reinterpret_cast<const float4*>(&sm->xs[i * XP]);
                float4 xa = xr[dq];
                float4 xb = xr[32 + dq];
                float wk[4] = {wv.x, wv.y, wv.z, wv.w};
                #pragma unroll
                for (int k = 0; k < 4; ++k) {
                    acc[k][0].x = fmaf(wk[k], xa.x, acc[k][0].x);
                    acc[k][0].y = fmaf(wk[k], xa.y, acc[k][0].y);
                    acc[k][0].z = fmaf(wk[k], xa.z, acc[k][0].z);
                    acc[k][0].w = fmaf(wk[k], xa.w, acc[k][0].w);
                    acc[k][1].x = fmaf(wk[k], xb.x, acc[k][1].x);
                    acc[k][1].y = fmaf(wk[k], xb.y, acc[k][1].y);
                    acc[k][1].z = fmaf(wk[k], xb.z, acc[k][1].z);
                    acc[k][1].w = fmaf(wk[k], xb.w, acc[k][1].w);
                }
            }
            // per-tile wsum for this warp's 4 k's
            float4 wp = make_float4(0.f, 0.f, 0.f, 0.f);
            for (int i = dq; i < TP; i += 32) {
                float4 wv = *reinterpret_cast<const float4*>(&sm->ws[i * WP + kq * 4]);
                wp.x += wv.x; wp.y += wv.y; wp.z += wv.z; wp.w += wv.w;
            }
            #pragma unroll
            for (int off = 16; off; off >>= 1) {
                wp.x += __shfl_xor_sync(0xffffffffu, wp.x, off);
                wp.y += __shfl_xor_sync(0xffffffffu, wp.y, off);
                wp.z += __shfl_xor_sync(0xffffffffu, wp.z, off);
                wp.w += __shfl_xor_sync(0xffffffffu, wp.w, off);
            }
            wsum.x += wp.x; wsum.y += wp.y; wsum.z += wp.z; wsum.w += wp.w;
        }
    }

    // ---- finalize: E = acc - wsum * C, atomic combine across the 16 slices
    float* outb = out + (size_t)b * (Kk * Dd);
    float wka[4] = {wsum.x, wsum.y, wsum.z, wsum.w};
    #pragma unroll
    for (int k = 0; k < 4; ++k) {
        int kk = kq * 4 + k;
        float wk = wka[k];
        const float4* crow = reinterpret_cast<const float4*>(&sm->Cs[kk * CP]);
        float4 c0 = crow[dq];
        float4 c1 = crow[32 + dq];
        float4 a0 = acc[k][0], a1 = acc[k][1];
        a0.x -= wk * c0.x; a0.y -= wk * c0.y; a0.z -= wk * c0.z; a0.w -= wk * c0.w;
        a1.x -= wk * c1.x; a1.y -= wk * c1.y; a1.z -= wk * c1.z; a1.w -= wk * c1.w;
        float* p0 = outb + kk * Dd + dq * 4;
        atomicAdd(p0 + 0, a0.x);
        atomicAdd(p0 + 1, a0.y);
        atomicAdd(p0 + 2, a0.z);
        atomicAdd(p0 + 3, a0.w);
        float* p1 = outb + kk * Dd + 128 + dq * 4;
        atomicAdd(p1 + 0, a1.x);
        atomicAdd(p1 + 1, a1.y);
        atomicAdd(p1 + 2, a1.z);
        atomicAdd(p1 + 3, a1.w);
    }
}

extern "C" void kernel_launch(void* const* d_in, const int* in_sizes, int n_in,
                              void* d_out, int out_size)
{
    const float* x = (const float*)d_in[0];
    const float* C = (const float*)d_in[1];
    const float* S = (const float*)d_in[2];
    float* out = (float*)d_out;

    cudaFuncSetAttribute(deepten_kernel,
                         cudaFuncAttributeMaxDynamicSharedMemorySize,
                         (int)sizeof(SmemLayout));
    cudaMemsetAsync(d_out, 0, (size_t)out_size * sizeof(float));

    dim3 grid(SPLIT, Bb);
    deepten_kernel<<<grid, NTHR, sizeof(SmemLayout)>>>(x, C, S, out);
}